// round 6
// baseline (speedup 1.0000x reference)
#include <cuda_runtime.h>
#include <cuda_bf16.h>

// Problem: B=16, C=64, H=128, W=128
//   masked_l1[b,c] = sum_hw |pre-gt| * mask ; nonzero[b,c] = count(mask!=0)
//   loss = sum_bc( masked_l1 / max(nonzero,1) ) / B
//
// R5: DRAM% measured invariant at ~71% across occ 46-96%, regs 32-56,
// MLP 2-12 => 5.65 TB/s is the memory wall for this pattern; kernel body is
// converged (201MB / 5.65TB/s = 35.6us). Remaining lever: the serialized
// post-stream tail. Replace the global-last 1024-element finalize reduce
// with hierarchical tickets:
//   - per-bc ticket (4 segs): last segment CTA divides s/max(cnt,1) and
//     atomicAdds into g_loss -- overlapped with the ongoing stream.
//   - global ticket (1024 bc): last bc writes out[0] = g_loss/B. Tail is
//     now one read+write instead of a latency-bound 1024-elem reduce.
// All scratch reset by owning last-CTAs => deterministic graph replays.
// Register budget back to R3's (256,8): best measured kernel time.

#define BATCH   16
#define CHAN    64
#define HW      (128 * 128)            // 16384 elems per (b,c)
#define NBC     (BATCH * CHAN)         // 1024
#define SEGS    4
#define NSEG    (NBC * SEGS)           // 4096 CTAs
#define SEG_V4  (HW / 4 / SEGS)        // 1024 float4 per segment
#define THREADS 256
#define V4_PER_THREAD (SEG_V4 / THREADS)  // 4

__device__ float    g_s[NBC];
__device__ float    g_cnt[NBC];
__device__ unsigned g_tk[NBC];
__device__ float    g_loss;
__device__ unsigned g_done;

__global__ __launch_bounds__(THREADS, 8)
void l1loss_kernel(const float4* __restrict__ pre,
                   const float4* __restrict__ gt,
                   const float4* __restrict__ mask,
                   float* __restrict__ out) {
    const int seg  = blockIdx.x;            // 0..4095
    const int bc   = seg >> 2;              // 0..1023
    const int part = seg & (SEGS - 1);      // 0..3
    const long base = (long)bc * (HW / 4) + (long)part * SEG_V4 + threadIdx.x;

    float s   = 0.0f;
    float cnt = 0.0f;

    #pragma unroll
    for (int i = 0; i < V4_PER_THREAD; i++) {
        const long idx = base + (long)i * THREADS;
        const float4 p = __ldcs(&pre[idx]);
        const float4 g = __ldcs(&gt[idx]);
        const float4 m = __ldcs(&mask[idx]);
        s += fabsf(p.x - g.x) * m.x;
        s += fabsf(p.y - g.y) * m.y;
        s += fabsf(p.z - g.z) * m.z;
        s += fabsf(p.w - g.w) * m.w;
        cnt += m.x + m.y;           // mask is exactly {0,1}: sum == count
        cnt += m.z + m.w;
    }

    // Warp reduce
    #pragma unroll
    for (int off = 16; off > 0; off >>= 1) {
        s   += __shfl_down_sync(0xFFFFFFFFu, s,   off);
        cnt += __shfl_down_sync(0xFFFFFFFFu, cnt, off);
    }

    __shared__ float sh_s[THREADS / 32];
    __shared__ float sh_c[THREADS / 32];
    const int lane = threadIdx.x & 31;
    const int wid  = threadIdx.x >> 5;
    if (lane == 0) { sh_s[wid] = s; sh_c[wid] = cnt; }
    __syncthreads();

    if (threadIdx.x < 32) {
        s   = (lane < THREADS / 32) ? sh_s[lane] : 0.0f;
        cnt = (lane < THREADS / 32) ? sh_c[lane] : 0.0f;
        #pragma unroll
        for (int off = 4; off > 0; off >>= 1) {
            s   += __shfl_down_sync(0xFFFFFFFFu, s,   off);
            cnt += __shfl_down_sync(0xFFFFFFFFu, cnt, off);
        }
        if (lane == 0) {
            // Accumulate segment partials into per-bc scratch.
            atomicAdd(&g_s[bc],   s);
            atomicAdd(&g_cnt[bc], cnt);
            __threadfence();
            // Per-bc ticket: 4th segment of this bc finalizes the bc.
            if (atomicAdd(&g_tk[bc], 1u) == (unsigned)(SEGS - 1)) {
                const float ss = __ldcg(&g_s[bc]);
                const float cc = __ldcg(&g_cnt[bc]);
                g_s[bc]   = 0.0f;                 // reset for next replay
                g_cnt[bc] = 0.0f;
                g_tk[bc]  = 0u;
                atomicAdd(&g_loss, ss / fmaxf(cc, 1.0f));
                __threadfence();
                // Global ticket: 1024th bc writes the scalar output.
                if (atomicAdd(&g_done, 1u) == (unsigned)(NBC - 1)) {
                    out[0] = __ldcg(&g_loss) * (1.0f / (float)BATCH);
                    g_loss = 0.0f;                // reset for next replay
                    g_done = 0u;
                }
            }
        }
    }
}

extern "C" void kernel_launch(void* const* d_in, const int* in_sizes, int n_in,
                              void* d_out, int out_size) {
    const float4* pre  = (const float4*)d_in[0];
    const float4* gt   = (const float4*)d_in[1];
    const float4* mask = (const float4*)d_in[2];
    float* out = (float*)d_out;

    l1loss_kernel<<<NSEG, THREADS>>>(pre, gt, mask, out);
}

// round 7
// speedup vs baseline: 1.6208x; 1.6208x over previous
#include <cuda_runtime.h>
#include <cuda_bf16.h>

// Problem: B=16, C=64, H=128, W=128
//   masked_l1[b,c] = sum_hw |pre-gt| * mask ; nonzero[b,c] = count(mask!=0)
//   loss = sum_bc( masked_l1 / max(nonzero,1) ) / B
//
// R7: REVERT to the R3 structure (best measured: 35.3us, DRAM 72%).
// Post-mortem of R5/R6 (59.9us, DRAM 41%): mid-stream GPU-scope
// __threadfence + dependent single-address atomic chains on 1024 CTAs'
// critical paths serialized the L2/LSU under full HBM load. Lesson:
// one fence per CTA AFTER its loads complete is fine; fence->atomic->fence
// chains interleaved with the stream are not.
// Kernel is at the measured memory wall: 201.3MB / 5.65TB/s = 35.6us
// (DRAM% invariant ~71% across occ 46-96%, regs 32-56, MLP 2-12).
// Only retained extras vs R3: cnt += m (mask exactly {0,1}) and
// load-batched finalize.

#define BATCH   16
#define CHAN    64
#define HW      (128 * 128)            // 16384 elems per (b,c)
#define NBC     (BATCH * CHAN)         // 1024
#define SEGS    4
#define NSEG    (NBC * SEGS)           // 4096 CTAs
#define SEG_V4  (HW / 4 / SEGS)        // 1024 float4 per segment
#define THREADS 256
#define V4_PER_THREAD (SEG_V4 / THREADS)  // 4

__device__ float    g_s[NBC];
__device__ float    g_cnt[NBC];
__device__ unsigned g_ctr;

__global__ __launch_bounds__(THREADS, 8)
void l1loss_kernel(const float4* __restrict__ pre,
                   const float4* __restrict__ gt,
                   const float4* __restrict__ mask,
                   float* __restrict__ out) {
    const int seg  = blockIdx.x;            // 0..4095
    const int bc   = seg >> 2;              // 0..1023
    const int part = seg & (SEGS - 1);      // 0..3
    const long base = (long)bc * (HW / 4) + (long)part * SEG_V4 + threadIdx.x;

    float s   = 0.0f;
    float cnt = 0.0f;

    #pragma unroll
    for (int i = 0; i < V4_PER_THREAD; i++) {
        const long idx = base + (long)i * THREADS;
        const float4 p = __ldcs(&pre[idx]);
        const float4 g = __ldcs(&gt[idx]);
        const float4 m = __ldcs(&mask[idx]);
        s += fabsf(p.x - g.x) * m.x;
        s += fabsf(p.y - g.y) * m.y;
        s += fabsf(p.z - g.z) * m.z;
        s += fabsf(p.w - g.w) * m.w;
        cnt += m.x + m.y;           // mask is exactly {0,1}: sum == count
        cnt += m.z + m.w;
    }

    // Warp reduce
    #pragma unroll
    for (int off = 16; off > 0; off >>= 1) {
        s   += __shfl_down_sync(0xFFFFFFFFu, s,   off);
        cnt += __shfl_down_sync(0xFFFFFFFFu, cnt, off);
    }

    __shared__ float sh_s[THREADS / 32];
    __shared__ float sh_c[THREADS / 32];
    __shared__ int   sh_last;
    const int lane = threadIdx.x & 31;
    const int wid  = threadIdx.x >> 5;
    if (lane == 0) { sh_s[wid] = s; sh_c[wid] = cnt; }
    __syncthreads();

    if (threadIdx.x < 32) {
        s   = (lane < THREADS / 32) ? sh_s[lane] : 0.0f;
        cnt = (lane < THREADS / 32) ? sh_c[lane] : 0.0f;
        #pragma unroll
        for (int off = 4; off > 0; off >>= 1) {
            s   += __shfl_down_sync(0xFFFFFFFFu, s,   off);
            cnt += __shfl_down_sync(0xFFFFFFFFu, cnt, off);
        }
        if (lane == 0) {
            atomicAdd(&g_s[bc],   s);
            atomicAdd(&g_cnt[bc], cnt);
            __threadfence();
            const unsigned old = atomicAdd(&g_ctr, 1u);
            sh_last = (old == (unsigned)(NSEG - 1)) ? 1 : 0;
        }
    }
    __syncthreads();

    // Last CTA finalizes: divide per-bc, sum, write scalar, reset scratch.
    if (sh_last) {
        // Batch the loads: each thread owns V=4 (bc) slots; issue all 8
        // loads before any divide.
        float ss[NBC / THREADS], cc[NBC / THREADS];
        #pragma unroll
        for (int j = 0; j < NBC / THREADS; j++) {
            const int i = threadIdx.x + j * THREADS;
            ss[j] = __ldcg(&g_s[i]);
            cc[j] = __ldcg(&g_cnt[i]);
        }
        float q = 0.0f;
        #pragma unroll
        for (int j = 0; j < NBC / THREADS; j++) {
            const int i = threadIdx.x + j * THREADS;
            q += ss[j] / fmaxf(cc[j], 1.0f);
            g_s[i]   = 0.0f;                      // reset for next replay
            g_cnt[i] = 0.0f;
        }
        #pragma unroll
        for (int off = 16; off > 0; off >>= 1)
            q += __shfl_down_sync(0xFFFFFFFFu, q, off);

        if (lane == 0) sh_s[wid] = q;
        __syncthreads();
        if (threadIdx.x < 32) {
            q = (lane < THREADS / 32) ? sh_s[lane] : 0.0f;
            #pragma unroll
            for (int off = 4; off > 0; off >>= 1)
                q += __shfl_down_sync(0xFFFFFFFFu, q, off);
            if (lane == 0) {
                out[0] = q * (1.0f / (float)BATCH);
                g_ctr  = 0;                       // reset ticket for next replay
            }
        }
    }
}

extern "C" void kernel_launch(void* const* d_in, const int* in_sizes, int n_in,
                              void* d_out, int out_size) {
    const float4* pre  = (const float4*)d_in[0];
    const float4* gt   = (const float4*)d_in[1];
    const float4* mask = (const float4*)d_in[2];
    float* out = (float*)d_out;

    l1loss_kernel<<<NSEG, THREADS>>>(pre, gt, mask, out);
}

// round 8
// speedup vs baseline: 1.7174x; 1.0596x over previous
#include <cuda_runtime.h>
#include <cuda_bf16.h>

// Problem: B=16, C=64, H=128, W=128
//   masked_l1[b,c] = sum_hw |pre-gt| * mask ; nonzero[b,c] = count(mask!=0)
//   loss = sum_bc( masked_l1 / max(nonzero,1) ) / B
//
// R8: kernel is at the measured HBM wall (~5.7 TB/s => 35.5us floor;
// DRAM% invariant ~72% across occ 46-96%, regs 32-56, MLP 2-12).
// Last lever: wave-quantization granularity. SEGS 4 -> 8 gives 8192 CTAs
// = 55.4/SM (1.8% integer imbalance vs 3.7%), shrinking the tail-wave
// straggler. Per-CTA: 2 float4/thread/tensor, 6 LDG.128 front-batched.
// Structure otherwise identical to the proven R3/R7 form: per-bc scratch
// atomics + ONE fence + global ticket, last CTA finalizes in-kernel and
// resets scratch (deterministic graph replays).

#define BATCH   16
#define CHAN    64
#define HW      (128 * 128)            // 16384 elems per (b,c)
#define NBC     (BATCH * CHAN)         // 1024
#define SEGS    8
#define NSEG    (NBC * SEGS)           // 8192 CTAs
#define SEG_V4  (HW / 4 / SEGS)        // 512 float4 per segment
#define THREADS 256
#define V4_PER_THREAD (SEG_V4 / THREADS)  // 2

__device__ float    g_s[NBC];
__device__ float    g_cnt[NBC];
__device__ unsigned g_ctr;

__global__ __launch_bounds__(THREADS, 8)
void l1loss_kernel(const float4* __restrict__ pre,
                   const float4* __restrict__ gt,
                   const float4* __restrict__ mask,
                   float* __restrict__ out) {
    const int seg  = blockIdx.x;            // 0..8191
    const int bc   = seg >> 3;              // 0..1023
    const int part = seg & (SEGS - 1);      // 0..7
    const long base = (long)bc * (HW / 4) + (long)part * SEG_V4 + threadIdx.x;

    // Front-batch all 6 LDG.128.
    float4 p[V4_PER_THREAD], g[V4_PER_THREAD], m[V4_PER_THREAD];
    #pragma unroll
    for (int i = 0; i < V4_PER_THREAD; i++) p[i] = __ldcs(&pre [base + (long)i * THREADS]);
    #pragma unroll
    for (int i = 0; i < V4_PER_THREAD; i++) g[i] = __ldcs(&gt  [base + (long)i * THREADS]);
    #pragma unroll
    for (int i = 0; i < V4_PER_THREAD; i++) m[i] = __ldcs(&mask[base + (long)i * THREADS]);

    float s   = 0.0f;
    float cnt = 0.0f;
    #pragma unroll
    for (int i = 0; i < V4_PER_THREAD; i++) {
        s += fabsf(p[i].x - g[i].x) * m[i].x;
        s += fabsf(p[i].y - g[i].y) * m[i].y;
        s += fabsf(p[i].z - g[i].z) * m[i].z;
        s += fabsf(p[i].w - g[i].w) * m[i].w;
        cnt += m[i].x + m[i].y;     // mask is exactly {0,1}: sum == count
        cnt += m[i].z + m[i].w;
    }

    // Warp reduce
    #pragma unroll
    for (int off = 16; off > 0; off >>= 1) {
        s   += __shfl_down_sync(0xFFFFFFFFu, s,   off);
        cnt += __shfl_down_sync(0xFFFFFFFFu, cnt, off);
    }

    __shared__ float sh_s[THREADS / 32];
    __shared__ float sh_c[THREADS / 32];
    __shared__ int   sh_last;
    const int lane = threadIdx.x & 31;
    const int wid  = threadIdx.x >> 5;
    if (lane == 0) { sh_s[wid] = s; sh_c[wid] = cnt; }
    __syncthreads();

    if (threadIdx.x < 32) {
        s   = (lane < THREADS / 32) ? sh_s[lane] : 0.0f;
        cnt = (lane < THREADS / 32) ? sh_c[lane] : 0.0f;
        #pragma unroll
        for (int off = 4; off > 0; off >>= 1) {
            s   += __shfl_down_sync(0xFFFFFFFFu, s,   off);
            cnt += __shfl_down_sync(0xFFFFFFFFu, cnt, off);
        }
        if (lane == 0) {
            atomicAdd(&g_s[bc],   s);
            atomicAdd(&g_cnt[bc], cnt);
            __threadfence();
            const unsigned old = atomicAdd(&g_ctr, 1u);
            sh_last = (old == (unsigned)(NSEG - 1)) ? 1 : 0;
        }
    }
    __syncthreads();

    // Last CTA finalizes: divide per-bc, sum, write scalar, reset scratch.
    if (sh_last) {
        float ss[NBC / THREADS], cc[NBC / THREADS];
        #pragma unroll
        for (int j = 0; j < NBC / THREADS; j++) {
            const int i = threadIdx.x + j * THREADS;
            ss[j] = __ldcg(&g_s[i]);
            cc[j] = __ldcg(&g_cnt[i]);
        }
        float q = 0.0f;
        #pragma unroll
        for (int j = 0; j < NBC / THREADS; j++) {
            const int i = threadIdx.x + j * THREADS;
            q += ss[j] / fmaxf(cc[j], 1.0f);
            g_s[i]   = 0.0f;                      // reset for next replay
            g_cnt[i] = 0.0f;
        }
        #pragma unroll
        for (int off = 16; off > 0; off >>= 1)
            q += __shfl_down_sync(0xFFFFFFFFu, q, off);

        if (lane == 0) sh_s[wid] = q;
        __syncthreads();
        if (threadIdx.x < 32) {
            q = (lane < THREADS / 32) ? sh_s[lane] : 0.0f;
            #pragma unroll
            for (int off = 4; off > 0; off >>= 1)
                q += __shfl_down_sync(0xFFFFFFFFu, q, off);
            if (lane == 0) {
                out[0] = q * (1.0f / (float)BATCH);
                g_ctr  = 0;                       // reset ticket for next replay
            }
        }
    }
}

extern "C" void kernel_launch(void* const* d_in, const int* in_sizes, int n_in,
                              void* d_out, int out_size) {
    const float4* pre  = (const float4*)d_in[0];
    const float4* gt   = (const float4*)d_in[1];
    const float4* mask = (const float4*)d_in[2];
    float* out = (float*)d_out;

    l1loss_kernel<<<NSEG, THREADS>>>(pre, gt, mask, out);
}